// round 13
// baseline (speedup 1.0000x reference)
#include <cuda_runtime.h>
#include <cuda_bf16.h>
#include <cuda_fp16.h>
#include <cstdint>

// Problem constants
#define NN   65536      // nodes
#define NE   2097152    // edges
#define VV   1000       // chord vocab
#define FIN  128
#define HID  256
#define FOUT 128
#define NG   256        // graphs
#define CAP  128        // max in-degree bucket capacity (mean 32)
#define NPW  8          // nodes per warp in agg kernels

// ---------------- scratch (static device globals; no runtime alloc) ----------
__device__ float    g_dis[NN];
__device__ int      g_cnt[NN];
__device__ int2     g_bkt [(size_t)NN * CAP];    // 64 MB (row, w-bits) -> (row, norm-bits)
__device__ __half   g_chord16[(size_t)VV * FIN]; // 256 KB (L1-hot gather table)
__device__ unsigned g_agg1p[(size_t)NN * FIN];   // 32 MB  pair-split {hi2,lo2}
__device__ unsigned g_h1p  [(size_t)NN * HID];   // 64 MB  pair-split {hi2,lo2}
__device__ __half   g_y2h  [(size_t)NN * FOUT];  // 16 MB  fp16 layer-2 pre-agg
__device__ uint2    g_w1s[128 * 128];            // W1 pair-split [k][n/2]
__device__ uint2    g_w2s[256 * 64];             // W2 pair-split [k][n/2]
__device__ int      g_gcnt[NG];

// ================= helpers ===================================================
__device__ __forceinline__ uint32_t smem_u32(const void* p) {
    uint32_t a;
    asm("{ .reg .u64 t; cvta.to.shared.u64 t, %1; cvt.u32.u64 %0, t; }" : "=r"(a) : "l"(p));
    return a;
}
__device__ __forceinline__ void ldsm4(uint32_t* r, uint32_t addr) {
    asm volatile("ldmatrix.sync.aligned.m8n8.x4.shared.b16 {%0,%1,%2,%3}, [%4];"
                 : "=r"(r[0]), "=r"(r[1]), "=r"(r[2]), "=r"(r[3]) : "r"(addr));
}
__device__ __forceinline__ void ldsm4t(uint32_t* r, uint32_t addr) {
    asm volatile("ldmatrix.sync.aligned.m8n8.x4.trans.shared.b16 {%0,%1,%2,%3}, [%4];"
                 : "=r"(r[0]), "=r"(r[1]), "=r"(r[2]), "=r"(r[3]) : "r"(addr));
}
__device__ __forceinline__ void mma_bf16(float* c, const uint32_t* a, const uint32_t* b) {
    asm volatile("mma.sync.aligned.m16n8k16.row.col.f32.bf16.bf16.f32 "
                 "{%0,%1,%2,%3}, {%4,%5,%6,%7}, {%8,%9}, {%0,%1,%2,%3};"
                 : "+f"(c[0]), "+f"(c[1]), "+f"(c[2]), "+f"(c[3])
                 : "r"(a[0]), "r"(a[1]), "r"(a[2]), "r"(a[3]), "r"(b[0]), "r"(b[1]));
}
// hi/lo bf16 pair split of two adjacent fp32 -> {hi2, lo2}
__device__ __forceinline__ uint2 pack_hl2(float x, float y) {
    __nv_bfloat16 hx = __float2bfloat16(x), hy = __float2bfloat16(y);
    __nv_bfloat16 lx = __float2bfloat16(x - __bfloat162float(hx));
    __nv_bfloat16 ly = __float2bfloat16(y - __bfloat162float(hy));
    uint2 r;
    r.x = (uint32_t)__bfloat16_as_ushort(hx) | ((uint32_t)__bfloat16_as_ushort(hy) << 16);
    r.y = (uint32_t)__bfloat16_as_ushort(lx) | ((uint32_t)__bfloat16_as_ushort(ly) << 16);
    return r;
}

// ---------------- init: scalars + chord->fp16 + W pre-split ------------------
__global__ void k_init(float* __restrict__ out, const float* __restrict__ chord,
                       const float* __restrict__ W1, const float* __restrict__ W2) {
    int i = blockIdx.x * blockDim.x + threadIdx.x;    // 131072 threads
    if (i < NN) g_cnt[i] = 0;
    if (i < NG) g_gcnt[i] = 0;
    if (i < NG * FOUT) out[i] = 0.0f;
    if (i < VV * FIN) g_chord16[i] = __float2half_rn(chord[i]);
    if (i < 128 * 128) {                              // W1 pairs
        int k = i >> 7, np = i & 127;
        g_w1s[i] = pack_hl2(W1[k * HID + np * 2], W1[k * HID + np * 2 + 1]);
    } else if (i < 128 * 128 + 256 * 64) {            // W2 pairs
        int j = i - 128 * 128;
        int k = j >> 6, np = j & 63;
        g_w2s[j] = pack_hl2(W2[k * FOUT + np * 2], W2[k * FOUT + np * 2 + 1]);
    }
}

// ---------------- single edge pass: bucket scatter only ----------------------
__global__ void k_prep(const int* __restrict__ ei, const float* __restrict__ ea) {
    int e = blockIdx.x * blockDim.x + threadIdx.x;
    if (e >= NE) return;
    int row = ei[e], col = ei[NE + e];
    int k = atomicAdd(&g_cnt[col], 1);
    if (k < CAP) g_bkt[(size_t)col * CAP + k] = make_int2(row, __float_as_int(ea[e]));
}

// ---------------- warp-per-node: deg from own bucket -> dis; graph counts ----
__global__ void k_dis(const int* __restrict__ batch) {
    int wid  = threadIdx.x >> 5, lane = threadIdx.x & 31;
    int w = blockIdx.x * 8 + wid;
    int cnt = g_cnt[w]; if (cnt > CAP) cnt = CAP;
    const int2* bk = g_bkt + (size_t)w * CAP;
    float s = 0.0f;
    for (int k = lane; k < cnt; k += 32) s += __int_as_float(bk[k].y);
#pragma unroll
    for (int o = 16; o; o >>= 1) s += __shfl_xor_sync(0xFFFFFFFFu, s, o);
    if (lane == 0) {
        g_dis[w] = rsqrtf(1.0f + s);          // self-loop weight 1
        atomicAdd(&g_gcnt[batch[w]], 1);
    }
}

// ---------------- agg1: 8 nodes/warp, staged byte-offsets, fp16 table --------
__global__ void k_agg1(const int* __restrict__ nidx) {
    __shared__ float2 st[8][CAP];
    int wid = threadIdx.x >> 5, lane = threadIdx.x & 31;
    int gw = blockIdx.x * 8 + wid;
    const char* Tb = (const char*)g_chord16 + lane * 8;   // lane-offset table base

    for (int w = gw * NPW; w < gw * NPW + NPW; w++) {
        float dcol = g_dis[w];
        int cnt = g_cnt[w]; if (cnt > CAP) cnt = CAP;
        int2* bk = g_bkt + (size_t)w * CAP;

        // stage: lane-parallel scalar pass; persist fp32 norm for agg2
        for (int k0 = 0; k0 < cnt; k0 += 32) {
            int k = k0 + lane;
            if (k < cnt) {
                int2 e = bk[k];
                float nrm = g_dis[e.x] * __int_as_float(e.y) * dcol;
                bk[k].y = __float_as_int(nrm);
                st[wid][k] = make_float2(__int_as_float(nidx[e.x] << 8), nrm);
            }
        }
        __syncwarp();

        // self term
        float s = dcol * dcol;
        uint2 u = *(const uint2*)(Tb + ((size_t)nidx[w] << 8));
        float2 f0 = __half22float2(*(__half2*)&u.x);
        float2 f1 = __half22float2(*(__half2*)&u.y);
        float ax = f0.x * s, ay = f0.y * s, az = f1.x * s, aw = f1.y * s;

        int k = 0;
        for (; k + 8 <= cnt; k += 8) {
            float2 p[8]; uint2 uu[8];
#pragma unroll
            for (int j = 0; j < 8; j++) p[j] = st[wid][k + j];
#pragma unroll
            for (int j = 0; j < 8; j++)
                uu[j] = *(const uint2*)(Tb + (size_t)(uint32_t)__float_as_int(p[j].x));
#pragma unroll
            for (int j = 0; j < 8; j++) {
                float2 a = __half22float2(*(__half2*)&uu[j].x);
                float2 b = __half22float2(*(__half2*)&uu[j].y);
                ax += p[j].y * a.x; ay += p[j].y * a.y;
                az += p[j].y * b.x; aw += p[j].y * b.y;
            }
        }
        for (; k < cnt; k++) {
            float2 p = st[wid][k];
            uint2 uv = *(const uint2*)(Tb + (size_t)(uint32_t)__float_as_int(p.x));
            float2 a = __half22float2(*(__half2*)&uv.x), b = __half22float2(*(__half2*)&uv.y);
            ax += p.y*a.x; ay += p.y*a.y; az += p.y*b.x; aw += p.y*b.y;
        }
        // pair-split output
        uint2 pa = pack_hl2(ax, ay), pb = pack_hl2(az, aw);
        ((uint4*)g_agg1p)[(size_t)w * 32 + lane] = make_uint4(pa.x, pa.y, pb.x, pb.y);
        __syncwarp();   // staging reuse fence
    }
}

// ---------------- agg2 + bias + relu + register-pooled mean-pool --------------
__global__ void k_agg2pool(const float* __restrict__ b2, const int* __restrict__ batch,
                           float* __restrict__ out) {
    __shared__ float2 st[8][CAP];
    int wid  = threadIdx.x >> 5, lane = threadIdx.x & 31;
    int gw = blockIdx.x * 8 + wid;
    const char* Tb = (const char*)g_y2h + lane * 8;

    int f = lane * 4;
    float bb0 = b2[f+0], bb1 = b2[f+1], bb2 = b2[f+2], bb3 = b2[f+3];
    int gcur = -1;
    float a0 = 0.0f, a1 = 0.0f, a2 = 0.0f, a3 = 0.0f;

    for (int w = gw * NPW; w < gw * NPW + NPW; w++) {
        float dcol = g_dis[w];
        int cnt = g_cnt[w]; if (cnt > CAP) cnt = CAP;
        const int2* bk = g_bkt + (size_t)w * CAP;

        // stage (byte-offset, norm); bucket already holds fp32 norm
        for (int k0 = 0; k0 < cnt; k0 += 32) {
            int k = k0 + lane;
            if (k < cnt) {
                int2 e = bk[k];
                st[wid][k] = make_float2(__int_as_float(e.x << 8), __int_as_float(e.y));
            }
        }
        __syncwarp();

        float s = dcol * dcol;
        uint2 u = *(const uint2*)(Tb + ((size_t)w << 8));
        float2 f0 = __half22float2(*(__half2*)&u.x);
        float2 f1 = __half22float2(*(__half2*)&u.y);
        float ax = f0.x * s, ay = f0.y * s, az = f1.x * s, aw = f1.y * s;

        int k = 0;
        for (; k + 8 <= cnt; k += 8) {
            float2 p[8]; uint2 uu[8];
#pragma unroll
            for (int j = 0; j < 8; j++) p[j] = st[wid][k + j];
#pragma unroll
            for (int j = 0; j < 8; j++)
                uu[j] = *(const uint2*)(Tb + (size_t)(uint32_t)__float_as_int(p[j].x));
#pragma unroll
            for (int j = 0; j < 8; j++) {
                float2 a = __half22float2(*(__half2*)&uu[j].x);
                float2 b = __half22float2(*(__half2*)&uu[j].y);
                ax += p[j].y * a.x; ay += p[j].y * a.y;
                az += p[j].y * b.x; aw += p[j].y * b.y;
            }
        }
        for (; k < cnt; k++) {
            float2 p = st[wid][k];
            uint2 uv = *(const uint2*)(Tb + (size_t)(uint32_t)__float_as_int(p.x));
            float2 a = __half22float2(*(__half2*)&uv.x), b = __half22float2(*(__half2*)&uv.y);
            ax += p.y*a.x; ay += p.y*a.y; az += p.y*b.x; aw += p.y*b.y;
        }

        // bias + relu, register pooling over contiguous same-graph nodes
        float v0 = fmaxf(ax + bb0, 0.0f);
        float v1 = fmaxf(ay + bb1, 0.0f);
        float v2 = fmaxf(az + bb2, 0.0f);
        float v3 = fmaxf(aw + bb3, 0.0f);
        int g = batch[w];
        if (g != gcur) {
            if (gcur >= 0) {
                atomicAdd(&out[gcur * FOUT + f+0], a0);
                atomicAdd(&out[gcur * FOUT + f+1], a1);
                atomicAdd(&out[gcur * FOUT + f+2], a2);
                atomicAdd(&out[gcur * FOUT + f+3], a3);
            }
            gcur = g; a0 = a1 = a2 = a3 = 0.0f;
        }
        a0 += v0; a1 += v1; a2 += v2; a3 += v3;
        __syncwarp();   // staging reuse fence
    }
    if (gcur >= 0) {
        atomicAdd(&out[gcur * FOUT + f+0], a0);
        atomicAdd(&out[gcur * FOUT + f+1], a1);
        atomicAdd(&out[gcur * FOUT + f+2], a2);
        atomicAdd(&out[gcur * FOUT + f+3], a3);
    }
}

__global__ void k_div(float* __restrict__ out) {
    int idx = blockIdx.x * blockDim.x + threadIdx.x;
    if (idx >= NG * FOUT) return;
    float c = (float)g_gcnt[idx >> 7];
    out[idx] = out[idx] / fmaxf(c, 1.0f);
}

// ================= HMMA bf16 GEMM, pair-split, K-chunk 64, 2 CTAs/SM =========
template<int KTOT, int NO, bool L1EPI>
__global__ void __launch_bounds__(256, 2) k_mmagemm(const uint4* __restrict__ Ap4,
                                                    const uint4* __restrict__ Ws4,
                                                    const float* __restrict__ bias,
                                                    void* __restrict__ Out) {
    constexpr int NCH = KTOT / 64;
    extern __shared__ __align__(1024) char sm[];
    const uint32_t sb = smem_u32(sm);
    const uint32_t OFF_AH = 0, OFF_AL = 16384, OFF_BH = 32768, OFF_BL = 49152;

    const int tid   = threadIdx.x;
    const int lane  = tid & 31, wid = tid >> 5;
    const int warpM = wid & 3,  warpN = wid >> 2;
    const int row0  = blockIdx.y * 128;
    const int col0  = blockIdx.x * 128;

    float acc[2][8][4];
#pragma unroll
    for (int a = 0; a < 2; a++)
#pragma unroll
        for (int b = 0; b < 8; b++)
#pragma unroll
            for (int c = 0; c < 4; c++) acc[a][b][c] = 0.0f;

    for (int ch = 0; ch < NCH; ch++) {
        if (ch) __syncthreads();
#pragma unroll 4
        for (int i = tid; i < 128 * 16; i += 256) {
            int r = i >> 4, q = i & 15;
            uint4 v = Ap4[(size_t)(row0 + r) * (KTOT / 4) + ch * 16 + q];
            uint32_t so = (uint32_t)(r * 128 + q * 8) ^ ((uint32_t)(r & 7) << 4);
            *(uint2*)(sm + OFF_AH + so) = make_uint2(v.x, v.z);
            *(uint2*)(sm + OFF_AL + so) = make_uint2(v.y, v.w);
        }
#pragma unroll 4
        for (int i = tid; i < 64 * 32; i += 256) {
            int k = i >> 5, q = i & 31;
            uint4 v = Ws4[(size_t)(ch * 64 + k) * (NO / 4) + (col0 >> 2) + q];
            uint32_t so = (uint32_t)(k * 256 + q * 8) ^ ((uint32_t)(k & 7) << 4);
            *(uint2*)(sm + OFF_BH + so) = make_uint2(v.x, v.z);
            *(uint2*)(sm + OFF_BL + so) = make_uint2(v.y, v.w);
        }
        __syncthreads();

        const int sub = lane >> 3, wi = lane & 7;
#pragma unroll
        for (int ks = 0; ks < 4; ks++) {
            const int kBase = ks * 16;
            uint32_t ah[2][4], al[2][4];
#pragma unroll
            for (int mt = 0; mt < 2; mt++) {
                int row  = warpM * 32 + mt * 16 + wi + (sub & 1) * 8;
                int kcol = kBase + (sub >> 1) * 8;
                uint32_t so = (uint32_t)(row * 128 + kcol * 2) ^ ((uint32_t)(row & 7) << 4);
                ldsm4(ah[mt], sb + OFF_AH + so);
                ldsm4(al[mt], sb + OFF_AL + so);
            }
#pragma unroll
            for (int ng = 0; ng < 4; ng++) {
                uint32_t bh[4], bl[4];
                int kr = kBase + (sub & 1) * 8 + wi;
                int nc = warpN * 64 + ng * 16 + (sub >> 1) * 8;
                uint32_t so = (uint32_t)(kr * 256 + nc * 2) ^ ((uint32_t)(kr & 7) << 4);
                ldsm4t(bh, sb + OFF_BH + so);
                ldsm4t(bl, sb + OFF_BL + so);
#pragma unroll
                for (int mt = 0; mt < 2; mt++)
#pragma unroll
                    for (int h = 0; h < 2; h++) {
                        int nt = ng * 2 + h;
                        mma_bf16(acc[mt][nt], ah[mt], bh + 2 * h);
                        mma_bf16(acc[mt][nt], ah[mt], bl + 2 * h);
                        mma_bf16(acc[mt][nt], al[mt], bh + 2 * h);
                    }
            }
        }
    }

    const int gr = lane >> 2, tig = lane & 3;
#pragma unroll
    for (int mt = 0; mt < 2; mt++) {
#pragma unroll
        for (int nt = 0; nt < 8; nt++) {
            int r  = row0 + warpM * 32 + mt * 16 + gr;
            int cc = col0 + warpN * 64 + nt * 8 + tig * 2;
            float* c = acc[mt][nt];
            if (L1EPI) {
                float b0 = bias[cc], b1 = bias[cc + 1];
                uint2 p0 = pack_hl2(fmaxf(c[0] + b0, 0.0f), fmaxf(c[1] + b1, 0.0f));
                uint2 p1 = pack_hl2(fmaxf(c[2] + b0, 0.0f), fmaxf(c[3] + b1, 0.0f));
                ((uint2*)Out)[(size_t)r * (NO / 2) + (cc >> 1)]       = p0;
                ((uint2*)Out)[(size_t)(r + 8) * (NO / 2) + (cc >> 1)] = p1;
            } else {
                __half2 q0 = __floats2half2_rn(c[0], c[1]);
                __half2 q1 = __floats2half2_rn(c[2], c[3]);
                *(__half2*)((__half*)Out + (size_t)r * NO + cc)       = q0;
                *(__half2*)((__half*)Out + (size_t)(r + 8) * NO + cc) = q1;
            }
        }
    }
}

// ---------------- launch ------------------------------------------------------
extern "C" void kernel_launch(void* const* d_in, const int* in_sizes, int n_in,
                              void* d_out, int out_size) {
    const float* chord = (const float*)d_in[0];
    const float* W1    = (const float*)d_in[1];
    const float* b1    = (const float*)d_in[2];
    const float* W2    = (const float*)d_in[3];
    const float* b2    = (const float*)d_in[4];
    const float* ea    = (const float*)d_in[5];
    const int*   nidx  = (const int*)d_in[6];
    const int*   ei    = (const int*)d_in[7];
    const int*   batch = (const int*)d_in[8];
    float* out = (float*)d_out;

    unsigned *p_agg1p, *p_h1p;
    __half   *p_y2h;
    uint2    *p_w1s, *p_w2s;
    cudaGetSymbolAddress((void**)&p_agg1p, g_agg1p);
    cudaGetSymbolAddress((void**)&p_h1p,   g_h1p);
    cudaGetSymbolAddress((void**)&p_y2h,   g_y2h);
    cudaGetSymbolAddress((void**)&p_w1s,   g_w1s);
    cudaGetSymbolAddress((void**)&p_w2s,   g_w2s);

    const int SMEM = 64 * 1024;   // 4 x 16KB tiles
    cudaFuncSetAttribute(k_mmagemm<FIN, HID, true>,   cudaFuncAttributeMaxDynamicSharedMemorySize, SMEM);
    cudaFuncSetAttribute(k_mmagemm<HID, FOUT, false>, cudaFuncAttributeMaxDynamicSharedMemorySize, SMEM);

    k_init    <<<512, 256>>>(out, chord, W1, W2);
    k_prep    <<<NE / 256, 256>>>(ei, ea);
    k_dis     <<<NN / 8, 256>>>(batch);
    k_agg1    <<<NN / (8 * NPW), 256>>>(nidx);              // 1024 blocks

    dim3 g1(HID / 128, NN / 128);    // (2, 512)
    k_mmagemm<FIN, HID, true ><<<g1, 256, SMEM>>>((const uint4*)p_agg1p, (const uint4*)p_w1s, b1, p_h1p);

    dim3 g2(FOUT / 128, NN / 128);   // (1, 512)
    k_mmagemm<HID, FOUT, false><<<g2, 256, SMEM>>>((const uint4*)p_h1p, (const uint4*)p_w2s, nullptr, p_y2h);

    k_agg2pool<<<NN / (8 * NPW), 256>>>(b2, batch, out);    // 1024 blocks
    k_div     <<<(NG * FOUT) / 256, 256>>>(out);
}

// round 14
// speedup vs baseline: 1.0762x; 1.0762x over previous
#include <cuda_runtime.h>
#include <cuda_bf16.h>
#include <cuda_fp16.h>
#include <cstdint>

// Problem constants
#define NN   65536      // nodes
#define NE   2097152    // edges
#define VV   1000       // chord vocab
#define FIN  128
#define HID  256
#define FOUT 128
#define NG   256        // graphs
#define CAP  128        // max in-degree bucket capacity (mean 32)

// ---------------- scratch (static device globals; no runtime alloc) ----------
__device__ float    g_deg[NN];
__device__ float    g_dis[NN];
__device__ int      g_cnt[NN];
__device__ int2     g_bkt [(size_t)NN * CAP];    // 64 MB (row, w-bits) -> (row, norm-bits)
__device__ __half   g_chord16[(size_t)VV * FIN]; // 256 KB (L1-hot gather table)
__device__ unsigned g_agg1p[(size_t)NN * FIN];   // 32 MB  pair-split {hi2,lo2}
__device__ unsigned g_h1p  [(size_t)NN * HID];   // 64 MB  pair-split {hi2,lo2}
__device__ __half   g_y2h  [(size_t)NN * FOUT];  // 16 MB  fp16 layer-2 pre-agg
__device__ uint2    g_w1s[128 * 128];            // W1 pair-split [k][n/2]
__device__ uint2    g_w2s[256 * 64];             // W2 pair-split [k][n/2]
__device__ int      g_gcnt[NG];

// ================= helpers ===================================================
__device__ __forceinline__ uint32_t smem_u32(const void* p) {
    uint32_t a;
    asm("{ .reg .u64 t; cvta.to.shared.u64 t, %1; cvt.u32.u64 %0, t; }" : "=r"(a) : "l"(p));
    return a;
}
__device__ __forceinline__ void ldsm4(uint32_t* r, uint32_t addr) {
    asm volatile("ldmatrix.sync.aligned.m8n8.x4.shared.b16 {%0,%1,%2,%3}, [%4];"
                 : "=r"(r[0]), "=r"(r[1]), "=r"(r[2]), "=r"(r[3]) : "r"(addr));
}
__device__ __forceinline__ void ldsm4t(uint32_t* r, uint32_t addr) {
    asm volatile("ldmatrix.sync.aligned.m8n8.x4.trans.shared.b16 {%0,%1,%2,%3}, [%4];"
                 : "=r"(r[0]), "=r"(r[1]), "=r"(r[2]), "=r"(r[3]) : "r"(addr));
}
__device__ __forceinline__ void mma_bf16(float* c, const uint32_t* a, const uint32_t* b) {
    asm volatile("mma.sync.aligned.m16n8k16.row.col.f32.bf16.bf16.f32 "
                 "{%0,%1,%2,%3}, {%4,%5,%6,%7}, {%8,%9}, {%0,%1,%2,%3};"
                 : "+f"(c[0]), "+f"(c[1]), "+f"(c[2]), "+f"(c[3])
                 : "r"(a[0]), "r"(a[1]), "r"(a[2]), "r"(a[3]), "r"(b[0]), "r"(b[1]));
}
// hi/lo bf16 pair split of two adjacent fp32 -> {hi2, lo2}
__device__ __forceinline__ uint2 pack_hl2(float x, float y) {
    __nv_bfloat16 hx = __float2bfloat16(x), hy = __float2bfloat16(y);
    __nv_bfloat16 lx = __float2bfloat16(x - __bfloat162float(hx));
    __nv_bfloat16 ly = __float2bfloat16(y - __bfloat162float(hy));
    uint2 r;
    r.x = (uint32_t)__bfloat16_as_ushort(hx) | ((uint32_t)__bfloat16_as_ushort(hy) << 16);
    r.y = (uint32_t)__bfloat16_as_ushort(lx) | ((uint32_t)__bfloat16_as_ushort(ly) << 16);
    return r;
}

// ---------------- init: scalars + chord->fp16 + W pre-split ------------------
__global__ void k_init(float* __restrict__ out, const float* __restrict__ chord,
                       const float* __restrict__ W1, const float* __restrict__ W2) {
    int i = blockIdx.x * blockDim.x + threadIdx.x;    // 131072 threads
    if (i < NN) { g_cnt[i] = 0; g_deg[i] = 1.0f; }    // self-loop weight 1
    if (i < NG) g_gcnt[i] = 0;
    if (i < NG * FOUT) out[i] = 0.0f;
    if (i < VV * FIN) g_chord16[i] = __float2half_rn(chord[i]);
    if (i < 128 * 128) {                              // W1 pairs
        int k = i >> 7, np = i & 127;
        g_w1s[i] = pack_hl2(W1[k * HID + np * 2], W1[k * HID + np * 2 + 1]);
    } else if (i < 128 * 128 + 256 * 64) {            // W2 pairs
        int j = i - 128 * 128;
        int k = j >> 6, np = j & 63;
        g_w2s[j] = pack_hl2(W2[k * FOUT + np * 2], W2[k * FOUT + np * 2 + 1]);
    }
}

// ---------------- single edge pass: bucket scatter + degree ------------------
__global__ void k_prep(const int* __restrict__ ei, const float* __restrict__ ea) {
    int e = blockIdx.x * blockDim.x + threadIdx.x;
    if (e >= NE) return;
    int row = ei[e], col = ei[NE + e];
    float wv = ea[e];
    atomicAdd(&g_deg[col], wv);                       // no-return REDG, cheap
    int k = atomicAdd(&g_cnt[col], 1);
    if (k < CAP) g_bkt[(size_t)col * CAP + k] = make_int2(row, __float_as_int(wv));
}

// ---------------- elementwise: dis + graph counts ----------------------------
__global__ void k_dis(const int* __restrict__ batch) {
    int i = blockIdx.x * blockDim.x + threadIdx.x;
    if (i >= NN) return;
    g_dis[i] = rsqrtf(g_deg[i]);
    atomicAdd(&g_gcnt[batch[i]], 1);
}

// ---------------- agg1: lane-paired LDG.128 gathers, fp16 table --------------
// Warp splits into two 16-lane halves; each half handles alternate edges with
// uint4 (8-half) loads; halves merged by shfl at the end.
__global__ void k_agg1(const int* __restrict__ nidx) {
    __shared__ float2 st[8][CAP];
    int wid = threadIdx.x >> 5, lane = threadIdx.x & 31;
    int half = lane >> 4, sub = lane & 15;
    int w = blockIdx.x * 8 + wid;
    const char* Tb = (const char*)g_chord16 + sub * 16;   // dims [8*sub, 8*sub+8)

    float dcol = g_dis[w];
    int cnt = g_cnt[w]; if (cnt > CAP) cnt = CAP;
    int2* bk = g_bkt + (size_t)w * CAP;

    // stage: lane-parallel scalar pass; persist fp32 norm for agg2
    for (int k0 = 0; k0 < cnt; k0 += 32) {
        int k = k0 + lane;
        if (k < cnt) {
            int2 e = bk[k];
            float nrm = g_dis[e.x] * __int_as_float(e.y) * dcol;
            bk[k].y = __float_as_int(nrm);
            st[wid][k] = make_float2(__int_as_float(nidx[e.x] << 8), nrm);
        }
    }
    __syncwarp();

    // self term (half 0 only contributes; half 1 scales by 0)
    float2 acc0, acc1, acc2, acc3;
    {
        float s = (half == 0) ? dcol * dcol : 0.0f;
        uint4 v = *(const uint4*)(Tb + ((size_t)nidx[w] << 8));
        float2 f0 = __half22float2(*(__half2*)&v.x);
        float2 f1 = __half22float2(*(__half2*)&v.y);
        float2 f2 = __half22float2(*(__half2*)&v.z);
        float2 f3 = __half22float2(*(__half2*)&v.w);
        acc0 = make_float2(f0.x * s, f0.y * s);
        acc1 = make_float2(f1.x * s, f1.y * s);
        acc2 = make_float2(f2.x * s, f2.y * s);
        acc3 = make_float2(f3.x * s, f3.y * s);
    }

    int k = 0;
    for (; k + 8 <= cnt; k += 8) {             // 4 edges per lane-half
        float2 p[4]; uint4 uu[4];
#pragma unroll
        for (int j = 0; j < 4; j++) p[j] = st[wid][k + 2 * j + half];
#pragma unroll
        for (int j = 0; j < 4; j++)
            uu[j] = *(const uint4*)(Tb + (size_t)(uint32_t)__float_as_int(p[j].x));
#pragma unroll
        for (int j = 0; j < 4; j++) {
            float n = p[j].y;
            float2 f0 = __half22float2(*(__half2*)&uu[j].x);
            float2 f1 = __half22float2(*(__half2*)&uu[j].y);
            float2 f2 = __half22float2(*(__half2*)&uu[j].z);
            float2 f3 = __half22float2(*(__half2*)&uu[j].w);
            acc0.x += n * f0.x; acc0.y += n * f0.y;
            acc1.x += n * f1.x; acc1.y += n * f1.y;
            acc2.x += n * f2.x; acc2.y += n * f2.y;
            acc3.x += n * f3.x; acc3.y += n * f3.y;
        }
    }
    for (; k < cnt; k += 2) {                  // tail: each half takes its parity
        int idx = k + half;
        if (idx < cnt) {
            float2 p = st[wid][idx];
            uint4 v = *(const uint4*)(Tb + (size_t)(uint32_t)__float_as_int(p.x));
            float n = p.y;
            float2 f0 = __half22float2(*(__half2*)&v.x);
            float2 f1 = __half22float2(*(__half2*)&v.y);
            float2 f2 = __half22float2(*(__half2*)&v.z);
            float2 f3 = __half22float2(*(__half2*)&v.w);
            acc0.x += n * f0.x; acc0.y += n * f0.y;
            acc1.x += n * f1.x; acc1.y += n * f1.y;
            acc2.x += n * f2.x; acc2.y += n * f2.y;
            acc3.x += n * f3.x; acc3.y += n * f3.y;
        }
    }

    // merge halves
    acc0.x += __shfl_xor_sync(0xFFFFFFFFu, acc0.x, 16);
    acc0.y += __shfl_xor_sync(0xFFFFFFFFu, acc0.y, 16);
    acc1.x += __shfl_xor_sync(0xFFFFFFFFu, acc1.x, 16);
    acc1.y += __shfl_xor_sync(0xFFFFFFFFu, acc1.y, 16);
    acc2.x += __shfl_xor_sync(0xFFFFFFFFu, acc2.x, 16);
    acc2.y += __shfl_xor_sync(0xFFFFFFFFu, acc2.y, 16);
    acc3.x += __shfl_xor_sync(0xFFFFFFFFu, acc3.x, 16);
    acc3.y += __shfl_xor_sync(0xFFFFFFFFu, acc3.y, 16);

    if (half == 0) {                           // lanes 0-15 write dims [8sub,8sub+8)
        uint2 pa = pack_hl2(acc0.x, acc0.y), pb = pack_hl2(acc1.x, acc1.y);
        uint2 pc = pack_hl2(acc2.x, acc2.y), pd = pack_hl2(acc3.x, acc3.y);
        ((uint4*)g_agg1p)[(size_t)w * 32 + sub * 2 + 0] = make_uint4(pa.x, pa.y, pb.x, pb.y);
        ((uint4*)g_agg1p)[(size_t)w * 32 + sub * 2 + 1] = make_uint4(pc.x, pc.y, pd.x, pd.y);
    }
}

// ---------------- agg2 + bias + relu + fused mean-pool (R12 form) -------------
__global__ void k_agg2pool(const float* __restrict__ b2, const int* __restrict__ batch,
                           float* __restrict__ out) {
    __shared__ float2 st[8][CAP];
    __shared__ float  sacc[8][FOUT];
    __shared__ int    sgid[8];
    int wid  = threadIdx.x >> 5, lane = threadIdx.x & 31;
    int w = blockIdx.x * 8 + wid;
    const uint2* T = (const uint2*)g_y2h;

    float dcol = g_dis[w];
    int cnt = g_cnt[w]; if (cnt > CAP) cnt = CAP;
    const int2* bk = g_bkt + (size_t)w * CAP;

    for (int k0 = 0; k0 < cnt; k0 += 32) {
        int k = k0 + lane;
        if (k < cnt) {
            int2 e = bk[k];
            st[wid][k] = make_float2(__int_as_float(e.x), __int_as_float(e.y));
        }
    }
    __syncwarp();

    float s = dcol * dcol;
    uint2 u = T[(size_t)w * 32 + lane];
    float2 f0 = __half22float2(*(__half2*)&u.x);
    float2 f1 = __half22float2(*(__half2*)&u.y);
    float ax = f0.x * s, ay = f0.y * s, az = f1.x * s, aw = f1.y * s;

    int k = 0;
    for (; k + 8 <= cnt; k += 8) {
        float2 p[8]; uint2 uu[8];
#pragma unroll
        for (int j = 0; j < 8; j++) p[j] = st[wid][k + j];
#pragma unroll
        for (int j = 0; j < 8; j++) uu[j] = T[(size_t)__float_as_int(p[j].x) * 32 + lane];
#pragma unroll
        for (int j = 0; j < 8; j++) {
            float2 a = __half22float2(*(__half2*)&uu[j].x);
            float2 b = __half22float2(*(__half2*)&uu[j].y);
            ax += p[j].y * a.x; ay += p[j].y * a.y;
            az += p[j].y * b.x; aw += p[j].y * b.y;
        }
    }
    for (; k < cnt; k++) {
        float2 p = st[wid][k];
        uint2 uv = T[(size_t)__float_as_int(p.x) * 32 + lane];
        float2 a = __half22float2(*(__half2*)&uv.x), b = __half22float2(*(__half2*)&uv.y);
        ax += p.y*a.x; ay += p.y*a.y; az += p.y*b.x; aw += p.y*b.y;
    }

    // bias + relu
    int f = lane * 4;
    float v0 = fmaxf(ax + b2[f+0], 0.0f);
    float v1 = fmaxf(ay + b2[f+1], 0.0f);
    float v2 = fmaxf(az + b2[f+2], 0.0f);
    float v3 = fmaxf(aw + b2[f+3], 0.0f);
    int g = batch[w];

    // block-level pool (batch sorted -> block almost always one graph)
    sacc[wid][f+0] = v0; sacc[wid][f+1] = v1; sacc[wid][f+2] = v2; sacc[wid][f+3] = v3;
    if (lane == 0) sgid[wid] = g;
    __syncthreads();
    bool uniform = (sgid[0] == sgid[7]);
    if (uniform) {
        if (threadIdx.x < FOUT) {
            float sum = 0.0f;
#pragma unroll
            for (int q = 0; q < 8; q++) sum += sacc[q][threadIdx.x];
            atomicAdd(&out[sgid[0] * FOUT + threadIdx.x], sum);
        }
    } else {
        atomicAdd(&out[g * FOUT + f+0], v0);
        atomicAdd(&out[g * FOUT + f+1], v1);
        atomicAdd(&out[g * FOUT + f+2], v2);
        atomicAdd(&out[g * FOUT + f+3], v3);
    }
}

__global__ void k_div(float* __restrict__ out) {
    int idx = blockIdx.x * blockDim.x + threadIdx.x;
    if (idx >= NG * FOUT) return;
    float c = (float)g_gcnt[idx >> 7];
    out[idx] = out[idx] / fmaxf(c, 1.0f);
}

// ================= HMMA bf16 GEMM, pair-split, K-chunk 64, 2 CTAs/SM =========
template<int KTOT, int NO, bool L1EPI>
__global__ void __launch_bounds__(256, 2) k_mmagemm(const uint4* __restrict__ Ap4,
                                                    const uint4* __restrict__ Ws4,
                                                    const float* __restrict__ bias,
                                                    void* __restrict__ Out) {
    constexpr int NCH = KTOT / 64;
    extern __shared__ __align__(1024) char sm[];
    const uint32_t sb = smem_u32(sm);
    const uint32_t OFF_AH = 0, OFF_AL = 16384, OFF_BH = 32768, OFF_BL = 49152;

    const int tid   = threadIdx.x;
    const int lane  = tid & 31, wid = tid >> 5;
    const int warpM = wid & 3,  warpN = wid >> 2;
    const int row0  = blockIdx.y * 128;
    const int col0  = blockIdx.x * 128;

    float acc[2][8][4];
#pragma unroll
    for (int a = 0; a < 2; a++)
#pragma unroll
        for (int b = 0; b < 8; b++)
#pragma unroll
            for (int c = 0; c < 4; c++) acc[a][b][c] = 0.0f;

    for (int ch = 0; ch < NCH; ch++) {
        if (ch) __syncthreads();
#pragma unroll 4
        for (int i = tid; i < 128 * 16; i += 256) {
            int r = i >> 4, q = i & 15;
            uint4 v = Ap4[(size_t)(row0 + r) * (KTOT / 4) + ch * 16 + q];
            uint32_t so = (uint32_t)(r * 128 + q * 8) ^ ((uint32_t)(r & 7) << 4);
            *(uint2*)(sm + OFF_AH + so) = make_uint2(v.x, v.z);
            *(uint2*)(sm + OFF_AL + so) = make_uint2(v.y, v.w);
        }
#pragma unroll 4
        for (int i = tid; i < 64 * 32; i += 256) {
            int k = i >> 5, q = i & 31;
            uint4 v = Ws4[(size_t)(ch * 64 + k) * (NO / 4) + (col0 >> 2) + q];
            uint32_t so = (uint32_t)(k * 256 + q * 8) ^ ((uint32_t)(k & 7) << 4);
            *(uint2*)(sm + OFF_BH + so) = make_uint2(v.x, v.z);
            *(uint2*)(sm + OFF_BL + so) = make_uint2(v.y, v.w);
        }
        __syncthreads();

        const int sub = lane >> 3, wi = lane & 7;
#pragma unroll
        for (int ks = 0; ks < 4; ks++) {
            const int kBase = ks * 16;
            uint32_t ah[2][4], al[2][4];
#pragma unroll
            for (int mt = 0; mt < 2; mt++) {
                int row  = warpM * 32 + mt * 16 + wi + (sub & 1) * 8;
                int kcol = kBase + (sub >> 1) * 8;
                uint32_t so = (uint32_t)(row * 128 + kcol * 2) ^ ((uint32_t)(row & 7) << 4);
                ldsm4(ah[mt], sb + OFF_AH + so);
                ldsm4(al[mt], sb + OFF_AL + so);
            }
#pragma unroll
            for (int ng = 0; ng < 4; ng++) {
                uint32_t bh[4], bl[4];
                int kr = kBase + (sub & 1) * 8 + wi;
                int nc = warpN * 64 + ng * 16 + (sub >> 1) * 8;
                uint32_t so = (uint32_t)(kr * 256 + nc * 2) ^ ((uint32_t)(kr & 7) << 4);
                ldsm4t(bh, sb + OFF_BH + so);
                ldsm4t(bl, sb + OFF_BL + so);
#pragma unroll
                for (int mt = 0; mt < 2; mt++)
#pragma unroll
                    for (int h = 0; h < 2; h++) {
                        int nt = ng * 2 + h;
                        mma_bf16(acc[mt][nt], ah[mt], bh + 2 * h);
                        mma_bf16(acc[mt][nt], ah[mt], bl + 2 * h);
                        mma_bf16(acc[mt][nt], al[mt], bh + 2 * h);
                    }
            }
        }
    }

    const int gr = lane >> 2, tig = lane & 3;
#pragma unroll
    for (int mt = 0; mt < 2; mt++) {
#pragma unroll
        for (int nt = 0; nt < 8; nt++) {
            int r  = row0 + warpM * 32 + mt * 16 + gr;
            int cc = col0 + warpN * 64 + nt * 8 + tig * 2;
            float* c = acc[mt][nt];
            if (L1EPI) {
                float b0 = bias[cc], b1 = bias[cc + 1];
                uint2 p0 = pack_hl2(fmaxf(c[0] + b0, 0.0f), fmaxf(c[1] + b1, 0.0f));
                uint2 p1 = pack_hl2(fmaxf(c[2] + b0, 0.0f), fmaxf(c[3] + b1, 0.0f));
                ((uint2*)Out)[(size_t)r * (NO / 2) + (cc >> 1)]       = p0;
                ((uint2*)Out)[(size_t)(r + 8) * (NO / 2) + (cc >> 1)] = p1;
            } else {
                __half2 q0 = __floats2half2_rn(c[0], c[1]);
                __half2 q1 = __floats2half2_rn(c[2], c[3]);
                *(__half2*)((__half*)Out + (size_t)r * NO + cc)       = q0;
                *(__half2*)((__half*)Out + (size_t)(r + 8) * NO + cc) = q1;
            }
        }
    }
}

// ---------------- launch ------------------------------------------------------
extern "C" void kernel_launch(void* const* d_in, const int* in_sizes, int n_in,
                              void* d_out, int out_size) {
    const float* chord = (const float*)d_in[0];
    const float* W1    = (const float*)d_in[1];
    const float* b1    = (const float*)d_in[2];
    const float* W2    = (const float*)d_in[3];
    const float* b2    = (const float*)d_in[4];
    const float* ea    = (const float*)d_in[5];
    const int*   nidx  = (const int*)d_in[6];
    const int*   ei    = (const int*)d_in[7];
    const int*   batch = (const int*)d_in[8];
    float* out = (float*)d_out;

    unsigned *p_agg1p, *p_h1p;
    __half   *p_y2h;
    uint2    *p_w1s, *p_w2s;
    cudaGetSymbolAddress((void**)&p_agg1p, g_agg1p);
    cudaGetSymbolAddress((void**)&p_h1p,   g_h1p);
    cudaGetSymbolAddress((void**)&p_y2h,   g_y2h);
    cudaGetSymbolAddress((void**)&p_w1s,   g_w1s);
    cudaGetSymbolAddress((void**)&p_w2s,   g_w2s);

    const int SMEM = 64 * 1024;   // 4 x 16KB tiles
    cudaFuncSetAttribute(k_mmagemm<FIN, HID, true>,   cudaFuncAttributeMaxDynamicSharedMemorySize, SMEM);
    cudaFuncSetAttribute(k_mmagemm<HID, FOUT, false>, cudaFuncAttributeMaxDynamicSharedMemorySize, SMEM);

    k_init    <<<512, 256>>>(out, chord, W1, W2);
    k_prep    <<<NE / 256, 256>>>(ei, ea);
    k_dis     <<<NN / 256, 256>>>(batch);
    k_agg1    <<<NN / 8, 256>>>(nidx);

    dim3 g1(HID / 128, NN / 128);    // (2, 512)
    k_mmagemm<FIN, HID, true ><<<g1, 256, SMEM>>>((const uint4*)p_agg1p, (const uint4*)p_w1s, b1, p_h1p);

    dim3 g2(FOUT / 128, NN / 128);   // (1, 512)
    k_mmagemm<HID, FOUT, false><<<g2, 256, SMEM>>>((const uint4*)p_h1p, (const uint4*)p_w2s, nullptr, p_y2h);

    k_agg2pool<<<NN / 8, 256>>>(b2, batch, out);
    k_div     <<<(NG * FOUT) / 256, 256>>>(out);
}

// round 16
// speedup vs baseline: 1.1178x; 1.0386x over previous
#include <cuda_runtime.h>
#include <cuda_bf16.h>
#include <cuda_fp16.h>
#include <cstdint>

// Problem constants
#define NN   65536      // nodes
#define NE   2097152    // edges
#define VV   1000       // chord vocab
#define FIN  128
#define HID  256
#define FOUT 128
#define NG   256        // graphs
#define CAP  128        // max in-degree bucket capacity (mean 32)

// ---------------- scratch (static device globals; no runtime alloc) ----------
__device__ float    g_dis[NN];
__device__ int      g_cnt[NN];
__device__ int2     g_bkt [(size_t)NN * CAP];    // 64 MB (row, w-bits) -> (row, norm-bits)
__device__ __half   g_chord16[(size_t)VV * FIN]; // 256 KB (L1-hot gather table)
__device__ unsigned g_agg1p[(size_t)NN * FIN];   // 32 MB  pair-split {hi2,lo2}
__device__ unsigned g_h1p  [(size_t)NN * HID];   // 64 MB  pair-split {hi2,lo2}
__device__ __half   g_y2h  [(size_t)NN * FOUT];  // 16 MB  fp16 layer-2 pre-agg
__device__ uint2    g_w1s[128 * 128];            // W1 pair-split [k][n/2]
__device__ uint2    g_w2s[256 * 64];             // W2 pair-split [k][n/2]
__device__ int      g_gcnt[NG];

// ================= helpers ===================================================
__device__ __forceinline__ uint32_t smem_u32(const void* p) {
    uint32_t a;
    asm("{ .reg .u64 t; cvta.to.shared.u64 t, %1; cvt.u32.u64 %0, t; }" : "=r"(a) : "l"(p));
    return a;
}
__device__ __forceinline__ void ldsm4(uint32_t* r, uint32_t addr) {
    asm volatile("ldmatrix.sync.aligned.m8n8.x4.shared.b16 {%0,%1,%2,%3}, [%4];"
                 : "=r"(r[0]), "=r"(r[1]), "=r"(r[2]), "=r"(r[3]) : "r"(addr));
}
__device__ __forceinline__ void ldsm4t(uint32_t* r, uint32_t addr) {
    asm volatile("ldmatrix.sync.aligned.m8n8.x4.trans.shared.b16 {%0,%1,%2,%3}, [%4];"
                 : "=r"(r[0]), "=r"(r[1]), "=r"(r[2]), "=r"(r[3]) : "r"(addr));
}
__device__ __forceinline__ void mma_bf16(float* c, const uint32_t* a, const uint32_t* b) {
    asm volatile("mma.sync.aligned.m16n8k16.row.col.f32.bf16.bf16.f32 "
                 "{%0,%1,%2,%3}, {%4,%5,%6,%7}, {%8,%9}, {%0,%1,%2,%3};"
                 : "+f"(c[0]), "+f"(c[1]), "+f"(c[2]), "+f"(c[3])
                 : "r"(a[0]), "r"(a[1]), "r"(a[2]), "r"(a[3]), "r"(b[0]), "r"(b[1]));
}
// hi/lo bf16 pair split of two adjacent fp32 -> {hi2, lo2}
__device__ __forceinline__ uint2 pack_hl2(float x, float y) {
    __nv_bfloat16 hx = __float2bfloat16(x), hy = __float2bfloat16(y);
    __nv_bfloat16 lx = __float2bfloat16(x - __bfloat162float(hx));
    __nv_bfloat16 ly = __float2bfloat16(y - __bfloat162float(hy));
    uint2 r;
    r.x = (uint32_t)__bfloat16_as_ushort(hx) | ((uint32_t)__bfloat16_as_ushort(hy) << 16);
    r.y = (uint32_t)__bfloat16_as_ushort(lx) | ((uint32_t)__bfloat16_as_ushort(ly) << 16);
    return r;
}

// ---------------- init: scalars + chord->fp16 + W pre-split ------------------
__global__ void k_init(float* __restrict__ out, const float* __restrict__ chord,
                       const float* __restrict__ W1, const float* __restrict__ W2) {
    int i = blockIdx.x * blockDim.x + threadIdx.x;    // 131072 threads
    if (i < NN) g_cnt[i] = 0;
    if (i < NG) g_gcnt[i] = 0;
    if (i < NG * FOUT) out[i] = 0.0f;
    if (i < VV * FIN) g_chord16[i] = __float2half_rn(chord[i]);
    if (i < 128 * 128) {                              // W1 pairs
        int k = i >> 7, np = i & 127;
        g_w1s[i] = pack_hl2(W1[k * HID + np * 2], W1[k * HID + np * 2 + 1]);
    } else if (i < 128 * 128 + 256 * 64) {            // W2 pairs
        int j = i - 128 * 128;
        int k = j >> 6, np = j & 63;
        g_w2s[j] = pack_hl2(W2[k * FOUT + np * 2], W2[k * FOUT + np * 2 + 1]);
    }
}

// ---------------- single edge pass: bucket scatter only ----------------------
__global__ void k_prep(const int* __restrict__ ei, const float* __restrict__ ea) {
    int e = blockIdx.x * blockDim.x + threadIdx.x;
    if (e >= NE) return;
    int row = ei[e], col = ei[NE + e];
    int k = atomicAdd(&g_cnt[col], 1);
    if (k < CAP) g_bkt[(size_t)col * CAP + k] = make_int2(row, __float_as_int(ea[e]));
}

// ---------------- warp-per-node: deg from own bucket -> dis; graph counts ----
__global__ void k_dis(const int* __restrict__ batch) {
    int wid  = threadIdx.x >> 5, lane = threadIdx.x & 31;
    int w = blockIdx.x * 8 + wid;
    int cnt = g_cnt[w]; if (cnt > CAP) cnt = CAP;
    const int2* bk = g_bkt + (size_t)w * CAP;
    float s = 0.0f;
    for (int k = lane; k < cnt; k += 32) s += __int_as_float(bk[k].y);
#pragma unroll
    for (int o = 16; o; o >>= 1) s += __shfl_xor_sync(0xFFFFFFFFu, s, o);
    if (lane == 0) {
        g_dis[w] = rsqrtf(1.0f + s);          // self-loop weight 1
        atomicAdd(&g_gcnt[batch[w]], 1);
    }
}

// ---------------- agg1: lane-paired LDG.128 gathers, fp16 table --------------
__global__ void k_agg1(const int* __restrict__ nidx) {
    __shared__ float2 st[8][CAP];
    int wid = threadIdx.x >> 5, lane = threadIdx.x & 31;
    int half = lane >> 4, sub = lane & 15;
    int w = blockIdx.x * 8 + wid;
    const char* Tb = (const char*)g_chord16 + sub * 16;   // dims [8*sub, 8*sub+8)

    float dcol = g_dis[w];
    int cnt = g_cnt[w]; if (cnt > CAP) cnt = CAP;
    int2* bk = g_bkt + (size_t)w * CAP;

    // stage: lane-parallel scalar pass; persist fp32 norm for agg2
    for (int k0 = 0; k0 < cnt; k0 += 32) {
        int k = k0 + lane;
        if (k < cnt) {
            int2 e = bk[k];
            float nrm = g_dis[e.x] * __int_as_float(e.y) * dcol;
            bk[k].y = __float_as_int(nrm);
            st[wid][k] = make_float2(__int_as_float(nidx[e.x] << 8), nrm);
        }
    }
    __syncwarp();

    // self term (half 0 only contributes; half 1 scales by 0)
    float2 acc0, acc1, acc2, acc3;
    {
        float s = (half == 0) ? dcol * dcol : 0.0f;
        uint4 v = *(const uint4*)(Tb + ((size_t)nidx[w] << 8));
        float2 f0 = __half22float2(*(__half2*)&v.x);
        float2 f1 = __half22float2(*(__half2*)&v.y);
        float2 f2 = __half22float2(*(__half2*)&v.z);
        float2 f3 = __half22float2(*(__half2*)&v.w);
        acc0 = make_float2(f0.x * s, f0.y * s);
        acc1 = make_float2(f1.x * s, f1.y * s);
        acc2 = make_float2(f2.x * s, f2.y * s);
        acc3 = make_float2(f3.x * s, f3.y * s);
    }

    int k = 0;
    for (; k + 8 <= cnt; k += 8) {             // 4 edges per lane-half
        float2 p[4]; uint4 uu[4];
#pragma unroll
        for (int j = 0; j < 4; j++) p[j] = st[wid][k + 2 * j + half];
#pragma unroll
        for (int j = 0; j < 4; j++)
            uu[j] = *(const uint4*)(Tb + (size_t)(uint32_t)__float_as_int(p[j].x));
#pragma unroll
        for (int j = 0; j < 4; j++) {
            float n = p[j].y;
            float2 f0 = __half22float2(*(__half2*)&uu[j].x);
            float2 f1 = __half22float2(*(__half2*)&uu[j].y);
            float2 f2 = __half22float2(*(__half2*)&uu[j].z);
            float2 f3 = __half22float2(*(__half2*)&uu[j].w);
            acc0.x += n * f0.x; acc0.y += n * f0.y;
            acc1.x += n * f1.x; acc1.y += n * f1.y;
            acc2.x += n * f2.x; acc2.y += n * f2.y;
            acc3.x += n * f3.x; acc3.y += n * f3.y;
        }
    }
    for (; k < cnt; k += 2) {                  // tail: each half takes its parity
        int idx = k + half;
        if (idx < cnt) {
            float2 p = st[wid][idx];
            uint4 v = *(const uint4*)(Tb + (size_t)(uint32_t)__float_as_int(p.x));
            float n = p.y;
            float2 f0 = __half22float2(*(__half2*)&v.x);
            float2 f1 = __half22float2(*(__half2*)&v.y);
            float2 f2 = __half22float2(*(__half2*)&v.z);
            float2 f3 = __half22float2(*(__half2*)&v.w);
            acc0.x += n * f0.x; acc0.y += n * f0.y;
            acc1.x += n * f1.x; acc1.y += n * f1.y;
            acc2.x += n * f2.x; acc2.y += n * f2.y;
            acc3.x += n * f3.x; acc3.y += n * f3.y;
        }
    }

    // merge halves
    acc0.x += __shfl_xor_sync(0xFFFFFFFFu, acc0.x, 16);
    acc0.y += __shfl_xor_sync(0xFFFFFFFFu, acc0.y, 16);
    acc1.x += __shfl_xor_sync(0xFFFFFFFFu, acc1.x, 16);
    acc1.y += __shfl_xor_sync(0xFFFFFFFFu, acc1.y, 16);
    acc2.x += __shfl_xor_sync(0xFFFFFFFFu, acc2.x, 16);
    acc2.y += __shfl_xor_sync(0xFFFFFFFFu, acc2.y, 16);
    acc3.x += __shfl_xor_sync(0xFFFFFFFFu, acc3.x, 16);
    acc3.y += __shfl_xor_sync(0xFFFFFFFFu, acc3.y, 16);

    if (half == 0) {                           // lanes 0-15 write dims [8sub,8sub+8)
        uint2 pa = pack_hl2(acc0.x, acc0.y), pb = pack_hl2(acc1.x, acc1.y);
        uint2 pc = pack_hl2(acc2.x, acc2.y), pd = pack_hl2(acc3.x, acc3.y);
        ((uint4*)g_agg1p)[(size_t)w * 32 + sub * 2 + 0] = make_uint4(pa.x, pa.y, pb.x, pb.y);
        ((uint4*)g_agg1p)[(size_t)w * 32 + sub * 2 + 1] = make_uint4(pc.x, pc.y, pd.x, pd.y);
    }
}

// ---------------- agg2 + bias + relu + fused mean-pool, lane-paired ----------
__global__ void k_agg2pool(const float* __restrict__ b2, const int* __restrict__ batch,
                           float* __restrict__ out) {
    __shared__ float2 st[8][CAP];
    __shared__ float  sacc[8][FOUT];
    __shared__ int    sgid[8];
    int wid  = threadIdx.x >> 5, lane = threadIdx.x & 31;
    int half = lane >> 4, sub = lane & 15;
    int w = blockIdx.x * 8 + wid;
    const char* Tb = (const char*)g_y2h + sub * 16;       // dims [8*sub, 8*sub+8)

    float dcol = g_dis[w];
    int cnt = g_cnt[w]; if (cnt > CAP) cnt = CAP;
    const int2* bk = g_bkt + (size_t)w * CAP;

    // stage (byte-offset, norm); bucket already holds fp32 norm
    for (int k0 = 0; k0 < cnt; k0 += 32) {
        int k = k0 + lane;
        if (k < cnt) {
            int2 e = bk[k];
            st[wid][k] = make_float2(__int_as_float(e.x << 8), __int_as_float(e.y));
        }
    }
    __syncwarp();

    float2 acc0, acc1, acc2, acc3;
    {
        float s = (half == 0) ? dcol * dcol : 0.0f;
        uint4 v = *(const uint4*)(Tb + ((size_t)w << 8));
        float2 f0 = __half22float2(*(__half2*)&v.x);
        float2 f1 = __half22float2(*(__half2*)&v.y);
        float2 f2 = __half22float2(*(__half2*)&v.z);
        float2 f3 = __half22float2(*(__half2*)&v.w);
        acc0 = make_float2(f0.x * s, f0.y * s);
        acc1 = make_float2(f1.x * s, f1.y * s);
        acc2 = make_float2(f2.x * s, f2.y * s);
        acc3 = make_float2(f3.x * s, f3.y * s);
    }

    int k = 0;
    for (; k + 8 <= cnt; k += 8) {
        float2 p[4]; uint4 uu[4];
#pragma unroll
        for (int j = 0; j < 4; j++) p[j] = st[wid][k + 2 * j + half];
#pragma unroll
        for (int j = 0; j < 4; j++)
            uu[j] = *(const uint4*)(Tb + (size_t)(uint32_t)__float_as_int(p[j].x));
#pragma unroll
        for (int j = 0; j < 4; j++) {
            float n = p[j].y;
            float2 f0 = __half22float2(*(__half2*)&uu[j].x);
            float2 f1 = __half22float2(*(__half2*)&uu[j].y);
            float2 f2 = __half22float2(*(__half2*)&uu[j].z);
            float2 f3 = __half22float2(*(__half2*)&uu[j].w);
            acc0.x += n * f0.x; acc0.y += n * f0.y;
            acc1.x += n * f1.x; acc1.y += n * f1.y;
            acc2.x += n * f2.x; acc2.y += n * f2.y;
            acc3.x += n * f3.x; acc3.y += n * f3.y;
        }
    }
    for (; k < cnt; k += 2) {
        int idx = k + half;
        if (idx < cnt) {
            float2 p = st[wid][idx];
            uint4 v = *(const uint4*)(Tb + (size_t)(uint32_t)__float_as_int(p.x));
            float n = p.y;
            float2 f0 = __half22float2(*(__half2*)&v.x);
            float2 f1 = __half22float2(*(__half2*)&v.y);
            float2 f2 = __half22float2(*(__half2*)&v.z);
            float2 f3 = __half22float2(*(__half2*)&v.w);
            acc0.x += n * f0.x; acc0.y += n * f0.y;
            acc1.x += n * f1.x; acc1.y += n * f1.y;
            acc2.x += n * f2.x; acc2.y += n * f2.y;
            acc3.x += n * f3.x; acc3.y += n * f3.y;
        }
    }

    // merge halves
    acc0.x += __shfl_xor_sync(0xFFFFFFFFu, acc0.x, 16);
    acc0.y += __shfl_xor_sync(0xFFFFFFFFu, acc0.y, 16);
    acc1.x += __shfl_xor_sync(0xFFFFFFFFu, acc1.x, 16);
    acc1.y += __shfl_xor_sync(0xFFFFFFFFu, acc1.y, 16);
    acc2.x += __shfl_xor_sync(0xFFFFFFFFu, acc2.x, 16);
    acc2.y += __shfl_xor_sync(0xFFFFFFFFu, acc2.y, 16);
    acc3.x += __shfl_xor_sync(0xFFFFFFFFu, acc3.x, 16);
    acc3.y += __shfl_xor_sync(0xFFFFFFFFu, acc3.y, 16);

    // bias + relu on half-0 lanes (8 dims each at [8sub, 8sub+8))
    int f = sub * 8;
    float vals[8];
    if (half == 0) {
        vals[0] = fmaxf(acc0.x + b2[f+0], 0.0f);
        vals[1] = fmaxf(acc0.y + b2[f+1], 0.0f);
        vals[2] = fmaxf(acc1.x + b2[f+2], 0.0f);
        vals[3] = fmaxf(acc1.y + b2[f+3], 0.0f);
        vals[4] = fmaxf(acc2.x + b2[f+4], 0.0f);
        vals[5] = fmaxf(acc2.y + b2[f+5], 0.0f);
        vals[6] = fmaxf(acc3.x + b2[f+6], 0.0f);
        vals[7] = fmaxf(acc3.y + b2[f+7], 0.0f);
#pragma unroll
        for (int j = 0; j < 8; j++) sacc[wid][f + j] = vals[j];
    }
    if (lane == 0) sgid[wid] = batch[w];
    __syncthreads();
    bool uniform = (sgid[0] == sgid[7]);
    if (uniform) {
        if (threadIdx.x < FOUT) {
            float sum = 0.0f;
#pragma unroll
            for (int q = 0; q < 8; q++) sum += sacc[q][threadIdx.x];
            atomicAdd(&out[sgid[0] * FOUT + threadIdx.x], sum);
        }
    } else if (half == 0) {
        int g = batch[w];
#pragma unroll
        for (int j = 0; j < 8; j++) atomicAdd(&out[g * FOUT + f + j], vals[j]);
    }
}

__global__ void k_div(float* __restrict__ out) {
    int idx = blockIdx.x * blockDim.x + threadIdx.x;
    if (idx >= NG * FOUT) return;
    float c = (float)g_gcnt[idx >> 7];
    out[idx] = out[idx] / fmaxf(c, 1.0f);
}

// ================= HMMA bf16 GEMM, pair-split, K-chunk 64, 2 CTAs/SM =========
template<int KTOT, int NO, bool L1EPI>
__global__ void __launch_bounds__(256, 2) k_mmagemm(const uint4* __restrict__ Ap4,
                                                    const uint4* __restrict__ Ws4,
                                                    const float* __restrict__ bias,
                                                    void* __restrict__ Out) {
    constexpr int NCH = KTOT / 64;
    extern __shared__ __align__(1024) char sm[];
    const uint32_t sb = smem_u32(sm);
    const uint32_t OFF_AH = 0, OFF_AL = 16384, OFF_BH = 32768, OFF_BL = 49152;

    const int tid   = threadIdx.x;
    const int lane  = tid & 31, wid = tid >> 5;
    const int warpM = wid & 3,  warpN = wid >> 2;
    const int row0  = blockIdx.y * 128;
    const int col0  = blockIdx.x * 128;

    float acc[2][8][4];
#pragma unroll
    for (int a = 0; a < 2; a++)
#pragma unroll
        for (int b = 0; b < 8; b++)
#pragma unroll
            for (int c = 0; c < 4; c++) acc[a][b][c] = 0.0f;

    for (int ch = 0; ch < NCH; ch++) {
        if (ch) __syncthreads();
#pragma unroll 4
        for (int i = tid; i < 128 * 16; i += 256) {
            int r = i >> 4, q = i & 15;
            uint4 v = Ap4[(size_t)(row0 + r) * (KTOT / 4) + ch * 16 + q];
            uint32_t so = (uint32_t)(r * 128 + q * 8) ^ ((uint32_t)(r & 7) << 4);
            *(uint2*)(sm + OFF_AH + so) = make_uint2(v.x, v.z);
            *(uint2*)(sm + OFF_AL + so) = make_uint2(v.y, v.w);
        }
#pragma unroll 4
        for (int i = tid; i < 64 * 32; i += 256) {
            int k = i >> 5, q = i & 31;
            uint4 v = Ws4[(size_t)(ch * 64 + k) * (NO / 4) + (col0 >> 2) + q];
            uint32_t so = (uint32_t)(k * 256 + q * 8) ^ ((uint32_t)(k & 7) << 4);
            *(uint2*)(sm + OFF_BH + so) = make_uint2(v.x, v.z);
            *(uint2*)(sm + OFF_BL + so) = make_uint2(v.y, v.w);
        }
        __syncthreads();

        const int sub = lane >> 3, wi = lane & 7;
#pragma unroll
        for (int ks = 0; ks < 4; ks++) {
            const int kBase = ks * 16;
            uint32_t ah[2][4], al[2][4];
#pragma unroll
            for (int mt = 0; mt < 2; mt++) {
                int row  = warpM * 32 + mt * 16 + wi + (sub & 1) * 8;
                int kcol = kBase + (sub >> 1) * 8;
                uint32_t so = (uint32_t)(row * 128 + kcol * 2) ^ ((uint32_t)(row & 7) << 4);
                ldsm4(ah[mt], sb + OFF_AH + so);
                ldsm4(al[mt], sb + OFF_AL + so);
            }
#pragma unroll
            for (int ng = 0; ng < 4; ng++) {
                uint32_t bh[4], bl[4];
                int kr = kBase + (sub & 1) * 8 + wi;
                int nc = warpN * 64 + ng * 16 + (sub >> 1) * 8;
                uint32_t so = (uint32_t)(kr * 256 + nc * 2) ^ ((uint32_t)(kr & 7) << 4);
                ldsm4t(bh, sb + OFF_BH + so);
                ldsm4t(bl, sb + OFF_BL + so);
#pragma unroll
                for (int mt = 0; mt < 2; mt++)
#pragma unroll
                    for (int h = 0; h < 2; h++) {
                        int nt = ng * 2 + h;
                        mma_bf16(acc[mt][nt], ah[mt], bh + 2 * h);
                        mma_bf16(acc[mt][nt], ah[mt], bl + 2 * h);
                        mma_bf16(acc[mt][nt], al[mt], bh + 2 * h);
                    }
            }
        }
    }

    const int gr = lane >> 2, tig = lane & 3;
#pragma unroll
    for (int mt = 0; mt < 2; mt++) {
#pragma unroll
        for (int nt = 0; nt < 8; nt++) {
            int r  = row0 + warpM * 32 + mt * 16 + gr;
            int cc = col0 + warpN * 64 + nt * 8 + tig * 2;
            float* c = acc[mt][nt];
            if (L1EPI) {
                float b0 = bias[cc], b1 = bias[cc + 1];
                uint2 p0 = pack_hl2(fmaxf(c[0] + b0, 0.0f), fmaxf(c[1] + b1, 0.0f));
                uint2 p1 = pack_hl2(fmaxf(c[2] + b0, 0.0f), fmaxf(c[3] + b1, 0.0f));
                ((uint2*)Out)[(size_t)r * (NO / 2) + (cc >> 1)]       = p0;
                ((uint2*)Out)[(size_t)(r + 8) * (NO / 2) + (cc >> 1)] = p1;
            } else {
                __half2 q0 = __floats2half2_rn(c[0], c[1]);
                __half2 q1 = __floats2half2_rn(c[2], c[3]);
                *(__half2*)((__half*)Out + (size_t)r * NO + cc)       = q0;
                *(__half2*)((__half*)Out + (size_t)(r + 8) * NO + cc) = q1;
            }
        }
    }
}

// ---------------- launch ------------------------------------------------------
extern "C" void kernel_launch(void* const* d_in, const int* in_sizes, int n_in,
                              void* d_out, int out_size) {
    const float* chord = (const float*)d_in[0];
    const float* W1    = (const float*)d_in[1];
    const float* b1    = (const float*)d_in[2];
    const float* W2    = (const float*)d_in[3];
    const float* b2    = (const float*)d_in[4];
    const float* ea    = (const float*)d_in[5];
    const int*   nidx  = (const int*)d_in[6];
    const int*   ei    = (const int*)d_in[7];
    const int*   batch = (const int*)d_in[8];
    float* out = (float*)d_out;

    unsigned *p_agg1p, *p_h1p;
    __half   *p_y2h;
    uint2    *p_w1s, *p_w2s;
    cudaGetSymbolAddress((void**)&p_agg1p, g_agg1p);
    cudaGetSymbolAddress((void**)&p_h1p,   g_h1p);
    cudaGetSymbolAddress((void**)&p_y2h,   g_y2h);
    cudaGetSymbolAddress((void**)&p_w1s,   g_w1s);
    cudaGetSymbolAddress((void**)&p_w2s,   g_w2s);

    const int SMEM = 64 * 1024;   // 4 x 16KB tiles
    cudaFuncSetAttribute(k_mmagemm<FIN, HID, true>,   cudaFuncAttributeMaxDynamicSharedMemorySize, SMEM);
    cudaFuncSetAttribute(k_mmagemm<HID, FOUT, false>, cudaFuncAttributeMaxDynamicSharedMemorySize, SMEM);

    k_init    <<<512, 256>>>(out, chord, W1, W2);
    k_prep    <<<NE / 256, 256>>>(ei, ea);
    k_dis     <<<NN / 8, 256>>>(batch);
    k_agg1    <<<NN / 8, 256>>>(nidx);

    dim3 g1(HID / 128, NN / 128);    // (2, 512)
    k_mmagemm<FIN, HID, true ><<<g1, 256, SMEM>>>((const uint4*)p_agg1p, (const uint4*)p_w1s, b1, p_h1p);

    dim3 g2(FOUT / 128, NN / 128);   // (1, 512)
    k_mmagemm<HID, FOUT, false><<<g2, 256, SMEM>>>((const uint4*)p_h1p, (const uint4*)p_w2s, nullptr, p_y2h);

    k_agg2pool<<<NN / 8, 256>>>(b2, batch, out);
    k_div     <<<(NG * FOUT) / 256, 256>>>(out);
}

// round 17
// speedup vs baseline: 1.1573x; 1.0353x over previous
#include <cuda_runtime.h>
#include <cuda_bf16.h>
#include <cuda_fp16.h>
#include <cstdint>

// Problem constants
#define NN   65536      // nodes
#define NE   2097152    // edges
#define VV   1000       // chord vocab
#define FIN  128
#define HID  256
#define FOUT 128
#define NG   256        // graphs
#define CAP  128        // max in-degree bucket capacity (mean 32)

// ---------------- scratch (static device globals; no runtime alloc) ----------
__device__ float         g_dis[NN];
__device__ int           g_cnt[NN];
__device__ int2          g_bkt [(size_t)NN * CAP];    // 64 MB (row, w-bits) -> (row, norm-bits)
__device__ __half        g_chord16[(size_t)VV * FIN]; // 256 KB (L1-hot gather table)
__device__ unsigned      g_agg1p[(size_t)NN * FIN];   // 32 MB  pair-split {hi2,lo2}
__device__ __nv_bfloat16 g_h1h [(size_t)NN * HID];    // 32 MB  bf16 hi-only layer-1 out
__device__ __half        g_y2h [(size_t)NN * FOUT];   // 16 MB  fp16 layer-2 pre-agg
__device__ uint2         g_w1s[128 * 128];            // W1 pair-split [k][n/2]
__device__ uint2         g_w2s[256 * 64];             // W2 pair-split [k][n/2]
__device__ int           g_gcnt[NG];

// ================= helpers ===================================================
__device__ __forceinline__ uint32_t smem_u32(const void* p) {
    uint32_t a;
    asm("{ .reg .u64 t; cvta.to.shared.u64 t, %1; cvt.u32.u64 %0, t; }" : "=r"(a) : "l"(p));
    return a;
}
__device__ __forceinline__ void ldsm4(uint32_t* r, uint32_t addr) {
    asm volatile("ldmatrix.sync.aligned.m8n8.x4.shared.b16 {%0,%1,%2,%3}, [%4];"
                 : "=r"(r[0]), "=r"(r[1]), "=r"(r[2]), "=r"(r[3]) : "r"(addr));
}
__device__ __forceinline__ void ldsm4t(uint32_t* r, uint32_t addr) {
    asm volatile("ldmatrix.sync.aligned.m8n8.x4.trans.shared.b16 {%0,%1,%2,%3}, [%4];"
                 : "=r"(r[0]), "=r"(r[1]), "=r"(r[2]), "=r"(r[3]) : "r"(addr));
}
__device__ __forceinline__ void mma_bf16(float* c, const uint32_t* a, const uint32_t* b) {
    asm volatile("mma.sync.aligned.m16n8k16.row.col.f32.bf16.bf16.f32 "
                 "{%0,%1,%2,%3}, {%4,%5,%6,%7}, {%8,%9}, {%0,%1,%2,%3};"
                 : "+f"(c[0]), "+f"(c[1]), "+f"(c[2]), "+f"(c[3])
                 : "r"(a[0]), "r"(a[1]), "r"(a[2]), "r"(a[3]), "r"(b[0]), "r"(b[1]));
}
// hi/lo bf16 pair split of two adjacent fp32 -> {hi2, lo2}
__device__ __forceinline__ uint2 pack_hl2(float x, float y) {
    __nv_bfloat16 hx = __float2bfloat16(x), hy = __float2bfloat16(y);
    __nv_bfloat16 lx = __float2bfloat16(x - __bfloat162float(hx));
    __nv_bfloat16 ly = __float2bfloat16(y - __bfloat162float(hy));
    uint2 r;
    r.x = (uint32_t)__bfloat16_as_ushort(hx) | ((uint32_t)__bfloat16_as_ushort(hy) << 16);
    r.y = (uint32_t)__bfloat16_as_ushort(lx) | ((uint32_t)__bfloat16_as_ushort(ly) << 16);
    return r;
}
__device__ __forceinline__ uint32_t pack_bf2(float x, float y) {
    __nv_bfloat162 v = __floats2bfloat162_rn(x, y);
    return *(uint32_t*)&v;
}

// ---------------- init: scalars + chord->fp16 + W pre-split ------------------
__global__ void k_init(float* __restrict__ out, const float* __restrict__ chord,
                       const float* __restrict__ W1, const float* __restrict__ W2) {
    int i = blockIdx.x * blockDim.x + threadIdx.x;    // 131072 threads
    if (i < NN) g_cnt[i] = 0;
    if (i < NG) g_gcnt[i] = 0;
    if (i < NG * FOUT) out[i] = 0.0f;
    if (i < VV * FIN) g_chord16[i] = __float2half_rn(chord[i]);
    if (i < 128 * 128) {                              // W1 pairs
        int k = i >> 7, np = i & 127;
        g_w1s[i] = pack_hl2(W1[k * HID + np * 2], W1[k * HID + np * 2 + 1]);
    } else if (i < 128 * 128 + 256 * 64) {            // W2 pairs
        int j = i - 128 * 128;
        int k = j >> 6, np = j & 63;
        g_w2s[j] = pack_hl2(W2[k * FOUT + np * 2], W2[k * FOUT + np * 2 + 1]);
    }
}

// ---------------- single edge pass: bucket scatter only ----------------------
__global__ void k_prep(const int* __restrict__ ei, const float* __restrict__ ea) {
    int e = blockIdx.x * blockDim.x + threadIdx.x;
    if (e >= NE) return;
    int row = ei[e], col = ei[NE + e];
    int k = atomicAdd(&g_cnt[col], 1);
    if (k < CAP) g_bkt[(size_t)col * CAP + k] = make_int2(row, __float_as_int(ea[e]));
}

// ---------------- warp-per-node: deg from own bucket -> dis; graph counts ----
__global__ void k_dis(const int* __restrict__ batch) {
    int wid  = threadIdx.x >> 5, lane = threadIdx.x & 31;
    int w = blockIdx.x * 8 + wid;
    int cnt = g_cnt[w]; if (cnt > CAP) cnt = CAP;
    const int2* bk = g_bkt + (size_t)w * CAP;
    float s = 0.0f;
    for (int k = lane; k < cnt; k += 32) s += __int_as_float(bk[k].y);
#pragma unroll
    for (int o = 16; o; o >>= 1) s += __shfl_xor_sync(0xFFFFFFFFu, s, o);
    if (lane == 0) {
        g_dis[w] = rsqrtf(1.0f + s);          // self-loop weight 1
        atomicAdd(&g_gcnt[batch[w]], 1);
    }
}

// ---------------- agg1: lane-paired LDG.128 gathers, fp16 table --------------
__global__ void k_agg1(const int* __restrict__ nidx) {
    __shared__ float2 st[8][CAP];
    int wid = threadIdx.x >> 5, lane = threadIdx.x & 31;
    int half = lane >> 4, sub = lane & 15;
    int w = blockIdx.x * 8 + wid;
    const char* Tb = (const char*)g_chord16 + sub * 16;   // dims [8*sub, 8*sub+8)

    float dcol = g_dis[w];
    int cnt = g_cnt[w]; if (cnt > CAP) cnt = CAP;
    int2* bk = g_bkt + (size_t)w * CAP;

    // stage: lane-parallel scalar pass; persist fp32 norm for agg2
    for (int k0 = 0; k0 < cnt; k0 += 32) {
        int k = k0 + lane;
        if (k < cnt) {
            int2 e = bk[k];
            float nrm = g_dis[e.x] * __int_as_float(e.y) * dcol;
            bk[k].y = __float_as_int(nrm);
            st[wid][k] = make_float2(__int_as_float(nidx[e.x] << 8), nrm);
        }
    }
    __syncwarp();

    // self term (half 0 only contributes; half 1 scales by 0)
    float2 acc0, acc1, acc2, acc3;
    {
        float s = (half == 0) ? dcol * dcol : 0.0f;
        uint4 v = *(const uint4*)(Tb + ((size_t)nidx[w] << 8));
        float2 f0 = __half22float2(*(__half2*)&v.x);
        float2 f1 = __half22float2(*(__half2*)&v.y);
        float2 f2 = __half22float2(*(__half2*)&v.z);
        float2 f3 = __half22float2(*(__half2*)&v.w);
        acc0 = make_float2(f0.x * s, f0.y * s);
        acc1 = make_float2(f1.x * s, f1.y * s);
        acc2 = make_float2(f2.x * s, f2.y * s);
        acc3 = make_float2(f3.x * s, f3.y * s);
    }

    int k = 0;
    for (; k + 8 <= cnt; k += 8) {             // 4 edges per lane-half
        float2 p[4]; uint4 uu[4];
#pragma unroll
        for (int j = 0; j < 4; j++) p[j] = st[wid][k + 2 * j + half];
#pragma unroll
        for (int j = 0; j < 4; j++)
            uu[j] = *(const uint4*)(Tb + (size_t)(uint32_t)__float_as_int(p[j].x));
#pragma unroll
        for (int j = 0; j < 4; j++) {
            float n = p[j].y;
            float2 f0 = __half22float2(*(__half2*)&uu[j].x);
            float2 f1 = __half22float2(*(__half2*)&uu[j].y);
            float2 f2 = __half22float2(*(__half2*)&uu[j].z);
            float2 f3 = __half22float2(*(__half2*)&uu[j].w);
            acc0.x += n * f0.x; acc0.y += n * f0.y;
            acc1.x += n * f1.x; acc1.y += n * f1.y;
            acc2.x += n * f2.x; acc2.y += n * f2.y;
            acc3.x += n * f3.x; acc3.y += n * f3.y;
        }
    }
    for (; k < cnt; k += 2) {                  // tail: each half takes its parity
        int idx = k + half;
        if (idx < cnt) {
            float2 p = st[wid][idx];
            uint4 v = *(const uint4*)(Tb + (size_t)(uint32_t)__float_as_int(p.x));
            float n = p.y;
            float2 f0 = __half22float2(*(__half2*)&v.x);
            float2 f1 = __half22float2(*(__half2*)&v.y);
            float2 f2 = __half22float2(*(__half2*)&v.z);
            float2 f3 = __half22float2(*(__half2*)&v.w);
            acc0.x += n * f0.x; acc0.y += n * f0.y;
            acc1.x += n * f1.x; acc1.y += n * f1.y;
            acc2.x += n * f2.x; acc2.y += n * f2.y;
            acc3.x += n * f3.x; acc3.y += n * f3.y;
        }
    }

    // merge halves
    acc0.x += __shfl_xor_sync(0xFFFFFFFFu, acc0.x, 16);
    acc0.y += __shfl_xor_sync(0xFFFFFFFFu, acc0.y, 16);
    acc1.x += __shfl_xor_sync(0xFFFFFFFFu, acc1.x, 16);
    acc1.y += __shfl_xor_sync(0xFFFFFFFFu, acc1.y, 16);
    acc2.x += __shfl_xor_sync(0xFFFFFFFFu, acc2.x, 16);
    acc2.y += __shfl_xor_sync(0xFFFFFFFFu, acc2.y, 16);
    acc3.x += __shfl_xor_sync(0xFFFFFFFFu, acc3.x, 16);
    acc3.y += __shfl_xor_sync(0xFFFFFFFFu, acc3.y, 16);

    if (half == 0) {                           // lanes 0-15 write dims [8sub,8sub+8)
        uint2 pa = pack_hl2(acc0.x, acc0.y), pb = pack_hl2(acc1.x, acc1.y);
        uint2 pc = pack_hl2(acc2.x, acc2.y), pd = pack_hl2(acc3.x, acc3.y);
        ((uint4*)g_agg1p)[(size_t)w * 32 + sub * 2 + 0] = make_uint4(pa.x, pa.y, pb.x, pb.y);
        ((uint4*)g_agg1p)[(size_t)w * 32 + sub * 2 + 1] = make_uint4(pc.x, pc.y, pd.x, pd.y);
    }
}

// ---------------- agg2 + bias + relu + fused mean-pool, lane-paired ----------
__global__ void k_agg2pool(const float* __restrict__ b2, const int* __restrict__ batch,
                           float* __restrict__ out) {
    __shared__ float2 st[8][CAP];
    __shared__ float  sacc[8][FOUT];
    __shared__ int    sgid[8];
    int wid  = threadIdx.x >> 5, lane = threadIdx.x & 31;
    int half = lane >> 4, sub = lane & 15;
    int w = blockIdx.x * 8 + wid;
    const char* Tb = (const char*)g_y2h + sub * 16;       // dims [8*sub, 8*sub+8)

    float dcol = g_dis[w];
    int cnt = g_cnt[w]; if (cnt > CAP) cnt = CAP;
    const int2* bk = g_bkt + (size_t)w * CAP;

    // stage (byte-offset, norm); bucket already holds fp32 norm
    for (int k0 = 0; k0 < cnt; k0 += 32) {
        int k = k0 + lane;
        if (k < cnt) {
            int2 e = bk[k];
            st[wid][k] = make_float2(__int_as_float(e.x << 8), __int_as_float(e.y));
        }
    }
    __syncwarp();

    float2 acc0, acc1, acc2, acc3;
    {
        float s = (half == 0) ? dcol * dcol : 0.0f;
        uint4 v = *(const uint4*)(Tb + ((size_t)w << 8));
        float2 f0 = __half22float2(*(__half2*)&v.x);
        float2 f1 = __half22float2(*(__half2*)&v.y);
        float2 f2 = __half22float2(*(__half2*)&v.z);
        float2 f3 = __half22float2(*(__half2*)&v.w);
        acc0 = make_float2(f0.x * s, f0.y * s);
        acc1 = make_float2(f1.x * s, f1.y * s);
        acc2 = make_float2(f2.x * s, f2.y * s);
        acc3 = make_float2(f3.x * s, f3.y * s);
    }

    int k = 0;
    for (; k + 8 <= cnt; k += 8) {
        float2 p[4]; uint4 uu[4];
#pragma unroll
        for (int j = 0; j < 4; j++) p[j] = st[wid][k + 2 * j + half];
#pragma unroll
        for (int j = 0; j < 4; j++)
            uu[j] = *(const uint4*)(Tb + (size_t)(uint32_t)__float_as_int(p[j].x));
#pragma unroll
        for (int j = 0; j < 4; j++) {
            float n = p[j].y;
            float2 f0 = __half22float2(*(__half2*)&uu[j].x);
            float2 f1 = __half22float2(*(__half2*)&uu[j].y);
            float2 f2 = __half22float2(*(__half2*)&uu[j].z);
            float2 f3 = __half22float2(*(__half2*)&uu[j].w);
            acc0.x += n * f0.x; acc0.y += n * f0.y;
            acc1.x += n * f1.x; acc1.y += n * f1.y;
            acc2.x += n * f2.x; acc2.y += n * f2.y;
            acc3.x += n * f3.x; acc3.y += n * f3.y;
        }
    }
    for (; k < cnt; k += 2) {
        int idx = k + half;
        if (idx < cnt) {
            float2 p = st[wid][idx];
            uint4 v = *(const uint4*)(Tb + (size_t)(uint32_t)__float_as_int(p.x));
            float n = p.y;
            float2 f0 = __half22float2(*(__half2*)&v.x);
            float2 f1 = __half22float2(*(__half2*)&v.y);
            float2 f2 = __half22float2(*(__half2*)&v.z);
            float2 f3 = __half22float2(*(__half2*)&v.w);
            acc0.x += n * f0.x; acc0.y += n * f0.y;
            acc1.x += n * f1.x; acc1.y += n * f1.y;
            acc2.x += n * f2.x; acc2.y += n * f2.y;
            acc3.x += n * f3.x; acc3.y += n * f3.y;
        }
    }

    // merge halves
    acc0.x += __shfl_xor_sync(0xFFFFFFFFu, acc0.x, 16);
    acc0.y += __shfl_xor_sync(0xFFFFFFFFu, acc0.y, 16);
    acc1.x += __shfl_xor_sync(0xFFFFFFFFu, acc1.x, 16);
    acc1.y += __shfl_xor_sync(0xFFFFFFFFu, acc1.y, 16);
    acc2.x += __shfl_xor_sync(0xFFFFFFFFu, acc2.x, 16);
    acc2.y += __shfl_xor_sync(0xFFFFFFFFu, acc2.y, 16);
    acc3.x += __shfl_xor_sync(0xFFFFFFFFu, acc3.x, 16);
    acc3.y += __shfl_xor_sync(0xFFFFFFFFu, acc3.y, 16);

    // bias + relu on half-0 lanes (8 dims each at [8sub, 8sub+8))
    int f = sub * 8;
    float vals[8];
    if (half == 0) {
        vals[0] = fmaxf(acc0.x + b2[f+0], 0.0f);
        vals[1] = fmaxf(acc0.y + b2[f+1], 0.0f);
        vals[2] = fmaxf(acc1.x + b2[f+2], 0.0f);
        vals[3] = fmaxf(acc1.y + b2[f+3], 0.0f);
        vals[4] = fmaxf(acc2.x + b2[f+4], 0.0f);
        vals[5] = fmaxf(acc2.y + b2[f+5], 0.0f);
        vals[6] = fmaxf(acc3.x + b2[f+6], 0.0f);
        vals[7] = fmaxf(acc3.y + b2[f+7], 0.0f);
#pragma unroll
        for (int j = 0; j < 8; j++) sacc[wid][f + j] = vals[j];
    }
    if (lane == 0) sgid[wid] = batch[w];
    __syncthreads();
    bool uniform = (sgid[0] == sgid[7]);
    if (uniform) {
        if (threadIdx.x < FOUT) {
            float sum = 0.0f;
#pragma unroll
            for (int q = 0; q < 8; q++) sum += sacc[q][threadIdx.x];
            atomicAdd(&out[sgid[0] * FOUT + threadIdx.x], sum);
        }
    } else if (half == 0) {
        int g = batch[w];
#pragma unroll
        for (int j = 0; j < 8; j++) atomicAdd(&out[g * FOUT + f + j], vals[j]);
    }
}

__global__ void k_div(float* __restrict__ out) {
    int idx = blockIdx.x * blockDim.x + threadIdx.x;
    if (idx >= NG * FOUT) return;
    float c = (float)g_gcnt[idx >> 7];
    out[idx] = out[idx] / fmaxf(c, 1.0f);
}

// ================= HMMA bf16 GEMM, K-chunk 64, 2 CTAs/SM =====================
// ALO=true : A is pair-split uint4 rows ({hi2,lo2}); 3 MMAs/step.
// ALO=false: A is plain bf16 row-major;             2 MMAs/step (AhBh + AhBl).
template<int KTOT, int NO, bool L1EPI, bool ALO>
__global__ void __launch_bounds__(256, 2) k_mmagemm(const void* __restrict__ Ap,
                                                    const uint4* __restrict__ Ws4,
                                                    const float* __restrict__ bias,
                                                    void* __restrict__ Out) {
    constexpr int NCH = KTOT / 64;
    extern __shared__ __align__(1024) char sm[];
    const uint32_t sb = smem_u32(sm);
    const uint32_t OFF_AH = 0, OFF_AL = 16384, OFF_BH = 32768, OFF_BL = 49152;

    const int tid   = threadIdx.x;
    const int lane  = tid & 31, wid = tid >> 5;
    const int warpM = wid & 3,  warpN = wid >> 2;
    const int row0  = blockIdx.y * 128;
    const int col0  = blockIdx.x * 128;

    float acc[2][8][4];
#pragma unroll
    for (int a = 0; a < 2; a++)
#pragma unroll
        for (int b = 0; b < 8; b++)
#pragma unroll
            for (int c = 0; c < 4; c++) acc[a][b][c] = 0.0f;

    for (int ch = 0; ch < NCH; ch++) {
        if (ch) __syncthreads();
        if (ALO) {
            // pair-split A: LDG.128 -> 2x STS.64 into hi/lo tiles
#pragma unroll 4
            for (int i = tid; i < 128 * 16; i += 256) {
                int r = i >> 4, q = i & 15;
                uint4 v = ((const uint4*)Ap)[(size_t)(row0 + r) * (KTOT / 4) + ch * 16 + q];
                uint32_t so = (uint32_t)(r * 128 + q * 8) ^ ((uint32_t)(r & 7) << 4);
                *(uint2*)(sm + OFF_AH + so) = make_uint2(v.x, v.z);
                *(uint2*)(sm + OFF_AL + so) = make_uint2(v.y, v.w);
            }
        } else {
            // plain bf16 A: direct 16B -> 16B swizzled copy
#pragma unroll 4
            for (int i = tid; i < 128 * 8; i += 256) {
                int r = i >> 3, u = i & 7;
                uint4 v = *(const uint4*)((const char*)Ap
                        + ((size_t)(row0 + r) * KTOT + ch * 64 + u * 8) * 2);
                uint32_t so = (uint32_t)(r * 128 + u * 16) ^ ((uint32_t)(r & 7) << 4);
                *(uint4*)(sm + OFF_AH + so) = v;
            }
        }
#pragma unroll 4
        for (int i = tid; i < 64 * 32; i += 256) {
            int k = i >> 5, q = i & 31;
            uint4 v = Ws4[(size_t)(ch * 64 + k) * (NO / 4) + (col0 >> 2) + q];
            uint32_t so = (uint32_t)(k * 256 + q * 8) ^ ((uint32_t)(k & 7) << 4);
            *(uint2*)(sm + OFF_BH + so) = make_uint2(v.x, v.z);
            *(uint2*)(sm + OFF_BL + so) = make_uint2(v.y, v.w);
        }
        __syncthreads();

        const int sub = lane >> 3, wi = lane & 7;
#pragma unroll
        for (int ks = 0; ks < 4; ks++) {
            const int kBase = ks * 16;
            uint32_t ah[2][4], al[2][4];
#pragma unroll
            for (int mt = 0; mt < 2; mt++) {
                int row  = warpM * 32 + mt * 16 + wi + (sub & 1) * 8;
                int kcol = kBase + (sub >> 1) * 8;
                uint32_t so = (uint32_t)(row * 128 + kcol * 2) ^ ((uint32_t)(row & 7) << 4);
                ldsm4(ah[mt], sb + OFF_AH + so);
                if (ALO) ldsm4(al[mt], sb + OFF_AL + so);
            }
#pragma unroll
            for (int ng = 0; ng < 4; ng++) {
                uint32_t bh[4], bl[4];
                int kr = kBase + (sub & 1) * 8 + wi;
                int nc = warpN * 64 + ng * 16 + (sub >> 1) * 8;
                uint32_t so = (uint32_t)(kr * 256 + nc * 2) ^ ((uint32_t)(kr & 7) << 4);
                ldsm4t(bh, sb + OFF_BH + so);
                ldsm4t(bl, sb + OFF_BL + so);
#pragma unroll
                for (int mt = 0; mt < 2; mt++)
#pragma unroll
                    for (int h = 0; h < 2; h++) {
                        int nt = ng * 2 + h;
                        mma_bf16(acc[mt][nt], ah[mt], bh + 2 * h);
                        mma_bf16(acc[mt][nt], ah[mt], bl + 2 * h);
                        if (ALO) mma_bf16(acc[mt][nt], al[mt], bh + 2 * h);
                    }
            }
        }
    }

    const int gr = lane >> 2, tig = lane & 3;
#pragma unroll
    for (int mt = 0; mt < 2; mt++) {
#pragma unroll
        for (int nt = 0; nt < 8; nt++) {
            int r  = row0 + warpM * 32 + mt * 16 + gr;
            int cc = col0 + warpN * 64 + nt * 8 + tig * 2;    // even
            float* c = acc[mt][nt];
            if (L1EPI) {
                // bias + relu, bf16 hi-only output
                float b0 = bias[cc], b1 = bias[cc + 1];
                uint32_t p0 = pack_bf2(fmaxf(c[0] + b0, 0.0f), fmaxf(c[1] + b1, 0.0f));
                uint32_t p1 = pack_bf2(fmaxf(c[2] + b0, 0.0f), fmaxf(c[3] + b1, 0.0f));
                ((uint32_t*)Out)[((size_t)r * NO + cc) >> 1]       = p0;
                ((uint32_t*)Out)[((size_t)(r + 8) * NO + cc) >> 1] = p1;
            } else {
                __half2 q0 = __floats2half2_rn(c[0], c[1]);
                __half2 q1 = __floats2half2_rn(c[2], c[3]);
                *(__half2*)((__half*)Out + (size_t)r * NO + cc)       = q0;
                *(__half2*)((__half*)Out + (size_t)(r + 8) * NO + cc) = q1;
            }
        }
    }
}

// ---------------- launch ------------------------------------------------------
extern "C" void kernel_launch(void* const* d_in, const int* in_sizes, int n_in,
                              void* d_out, int out_size) {
    const float* chord = (const float*)d_in[0];
    const float* W1    = (const float*)d_in[1];
    const float* b1    = (const float*)d_in[2];
    const float* W2    = (const float*)d_in[3];
    const float* b2    = (const float*)d_in[4];
    const float* ea    = (const float*)d_in[5];
    const int*   nidx  = (const int*)d_in[6];
    const int*   ei    = (const int*)d_in[7];
    const int*   batch = (const int*)d_in[8];
    float* out = (float*)d_out;

    unsigned      *p_agg1p;
    __nv_bfloat16 *p_h1h;
    __half        *p_y2h;
    uint2         *p_w1s, *p_w2s;
    cudaGetSymbolAddress((void**)&p_agg1p, g_agg1p);
    cudaGetSymbolAddress((void**)&p_h1h,   g_h1h);
    cudaGetSymbolAddress((void**)&p_y2h,   g_y2h);
    cudaGetSymbolAddress((void**)&p_w1s,   g_w1s);
    cudaGetSymbolAddress((void**)&p_w2s,   g_w2s);

    const int SMEM = 64 * 1024;   // 4 x 16KB tiles
    cudaFuncSetAttribute(k_mmagemm<FIN, HID, true,  true >, cudaFuncAttributeMaxDynamicSharedMemorySize, SMEM);
    cudaFuncSetAttribute(k_mmagemm<HID, FOUT, false, false>, cudaFuncAttributeMaxDynamicSharedMemorySize, SMEM);

    k_init    <<<512, 256>>>(out, chord, W1, W2);
    k_prep    <<<NE / 256, 256>>>(ei, ea);
    k_dis     <<<NN / 8, 256>>>(batch);
    k_agg1    <<<NN / 8, 256>>>(nidx);

    dim3 g1(HID / 128, NN / 128);    // (2, 512)
    k_mmagemm<FIN, HID, true,  true ><<<g1, 256, SMEM>>>(p_agg1p, (const uint4*)p_w1s, b1, p_h1h);

    dim3 g2(FOUT / 128, NN / 128);   // (1, 512)
    k_mmagemm<HID, FOUT, false, false><<<g2, 256, SMEM>>>(p_h1h, (const uint4*)p_w2s, nullptr, p_y2h);

    k_agg2pool<<<NN / 8, 256>>>(b2, batch, out);
    k_div     <<<(NG * FOUT) / 256, 256>>>(out);
}